// round 6
// baseline (speedup 1.0000x reference)
#include <cuda_runtime.h>
#include <cstdint>

#define TT 1024
#define DD 64
#define HH 256
#define OO 128
#define THREADS 512

typedef unsigned long long ull;

// smem float offsets (static, ~41.5 KB)
#define OFF_WX1 0        // [64][68]  padded Wx1 slice
#define OFF_XT  4352     // [2][384]  swizzled xT: slot s_x(k)=k+(k>>1), entry *4+m
#define OFF_H1  5120     // [2][1152] swizzled h:  slot s_h(k)=k+(k>>3), entry *4+m
#define OFF_H2  7424     // [2][1152]
#define OFF_SCR 9728     // [640] epilogue scratch
#define OFF_MBAR 10368   // 2 x u64
#define SMEM_FLOATS 10372
#define MBAR1_B (OFF_MBAR * 4)
#define MBAR2_B (OFF_MBAR * 4 + 8)

__device__ __forceinline__ ull ffma2(ull a, ull b, ull c) {
    ull d; asm("fma.rn.f32x2 %0,%1,%2,%3;" : "=l"(d) : "l"(a), "l"(b), "l"(c)); return d;
}
__device__ __forceinline__ ull addf2(ull a, ull b) {
    ull d; asm("add.rn.f32x2 %0,%1,%2;" : "=l"(d) : "l"(a), "l"(b)); return d;
}
__device__ __forceinline__ ull pk2(float lo, float hi) {
    ull d; asm("mov.b64 %0,{%1,%2};" : "=l"(d) : "f"(lo), "f"(hi)); return d;
}
__device__ __forceinline__ void up2(ull a, float& lo, float& hi) {
    asm("mov.b64 {%0,%1},%2;" : "=f"(lo), "=f"(hi) : "l"(a));
}
__device__ __forceinline__ uint32_t s2u(const void* p) {
    uint32_t a;
    asm("{.reg .u64 t; cvta.to.shared.u64 t, %1; cvt.u32.u64 %0, t;}" : "=r"(a) : "l"(p));
    return a;
}
__device__ __forceinline__ void mbar_init(uint32_t m, uint32_t cnt) {
    asm volatile("mbarrier.init.shared.b64 [%0], %1;" :: "r"(m), "r"(cnt) : "memory");
}
__device__ __forceinline__ void mbar_expect(uint32_t m, uint32_t bytes) {
    asm volatile("mbarrier.arrive.expect_tx.shared.b64 _, [%0], %1;" :: "r"(m), "r"(bytes) : "memory");
}
__device__ __forceinline__ void mbar_wait(uint32_t m, uint32_t parity) {
    asm volatile(
        "{\n\t.reg .pred P;\n"
        "W%=:\n\t"
        "mbarrier.try_wait.parity.acquire.cta.shared::cta.b64 P, [%0], %1, 0x989680;\n\t"
        "@!P bra W%=;\n\t}"
        :: "r"(m), "r"(parity) : "memory");
}
#define CLUSTER_SYNC() do { \
    asm volatile("barrier.cluster.arrive.aligned;" ::: "memory"); \
    asm volatile("barrier.cluster.wait.aligned;" ::: "memory"); } while (0)

// 8 k-steps vs register weights (4 cols). hb: byte addr of this lane's h slice
// (16B slots, contiguous after swizzle). acc[2c]=cols c m01, acc[2c+1]=m23.
__device__ __forceinline__ void accumR(const float (&wt)[32], uint32_t hb, ull (&acc)[8]) {
#pragma unroll
    for (int i = 0; i < 8; i++) {
        ull H01, H23;
        asm("ld.shared.v2.u64 {%0,%1},[%2];" : "=l"(H01), "=l"(H23) : "r"(hb + 16 * i));
#pragma unroll
        for (int c = 0; c < 4; c++) {
            ull wd = pk2(wt[c * 8 + i], wt[c * 8 + i]);
            acc[2 * c]     = ffma2(wd, H01, acc[2 * c]);
            acc[2 * c + 1] = ffma2(wd, H23, acc[2 * c + 1]);
        }
    }
}

// 2 k-steps of x-projection (Wx1 from padded smem)
__device__ __forceinline__ void accumX(uint32_t wxb, int w, int lane, uint32_t xb,
                                       ull (&acc)[8]) {
#pragma unroll
    for (int i = 0; i < 2; i++) {
        ull X01, X23;
        asm("ld.shared.v2.u64 {%0,%1},[%2];" : "=l"(X01), "=l"(X23)
            : "r"(xb + 16 * (3 * lane + i)));
        float w0, w1, w2, w3;
        uint32_t wa = wxb + 4u * ((uint32_t)(2 * lane + i) * 68u + 4u * (uint32_t)w);
        asm("ld.shared.v4.f32 {%0,%1,%2,%3},[%4];"
            : "=f"(w0), "=f"(w1), "=f"(w2), "=f"(w3) : "r"(wa));
        ull d0 = pk2(w0, w0), d1 = pk2(w1, w1), d2 = pk2(w2, w2), d3 = pk2(w3, w3);
        acc[0] = ffma2(d0, X01, acc[0]); acc[1] = ffma2(d0, X23, acc[1]);
        acc[2] = ffma2(d1, X01, acc[2]); acc[3] = ffma2(d1, X23, acc[3]);
        acc[4] = ffma2(d2, X01, acc[4]); acc[5] = ffma2(d2, X23, acc[5]);
        acc[6] = ffma2(d3, X01, acc[6]); acc[7] = ffma2(d3, X23, acc[7]);
    }
}

// Intra-warp tree: reduce 32 k-lanes; afterwards acc[0]=m01, acc[1]=m23 of the
// lane's column (col_local = 4w + (lane>>3)), fully summed, in every lane.
__device__ __forceinline__ void wreduce(ull (&acc)[8], int lane) {
    bool lo16 = (lane & 16) == 0;
#pragma unroll
    for (int j = 0; j < 4; j++) {
        ull v = lo16 ? acc[4 + j] : acc[j];
        ull r = __shfl_xor_sync(0xffffffffu, v, 16);
        ull k = lo16 ? acc[j] : acc[4 + j];
        acc[j] = addf2(k, r);
    }
    bool lo8 = (lane & 8) == 0;
#pragma unroll
    for (int j = 0; j < 2; j++) {
        ull v = lo8 ? acc[2 + j] : acc[j];
        ull r = __shfl_xor_sync(0xffffffffu, v, 8);
        ull k = lo8 ? acc[j] : acc[2 + j];
        acc[j] = addf2(k, r);
    }
#pragma unroll
    for (int d = 4; d >= 1; d >>= 1) {
        acc[0] = addf2(acc[0], __shfl_xor_sync(0xffffffffu, acc[0], d));
        acc[1] = addf2(acc[1], __shfl_xor_sync(0xffffffffu, acc[1], d));
    }
}

// bias + tanh + packed b64 st.async broadcast (2 finalizer lanes per column)
__device__ __forceinline__ void finalize(const ull (&acc)[8], int lane, float bias,
                                         uint32_t su, uint32_t doff_b, uint32_t sh16,
                                         uint32_t mbar_b) {
    int sel = lane & 7;
    if (sel < 2) {
        float x0, x1;
        up2(sel == 0 ? acc[0] : acc[1], x0, x1);
        float f0 = tanhf(x0 + bias), f1 = tanhf(x1 + bias);
        ull hv = pk2(f0, f1);
        uint32_t off = doff_b + sh16 + 8u * (uint32_t)sel;
#pragma unroll
        for (int r = 0; r < 4; r++) {
            uint32_t pr;
            asm("mapa.shared::cluster.u32 %0,%1,%2;" : "=r"(pr) : "r"(su), "r"(r));
            asm volatile(
                "st.async.shared::cluster.mbarrier::complete_tx::bytes.b64 [%0],%1,[%2];"
                :: "r"(pr + off), "l"(hv), "r"(pr + mbar_b) : "memory");
        }
    }
}

__global__ void __launch_bounds__(THREADS, 1) __cluster_dims__(4, 1, 1)
rnn_kernel(const float* __restrict__ x, const float* __restrict__ Wx1,
           const float* __restrict__ Wh1, const float* __restrict__ b1,
           const float* __restrict__ Wx2, const float* __restrict__ Wh2,
           const float* __restrict__ b2, const float* __restrict__ Wd,
           const float* __restrict__ bd, float* __restrict__ out) {
    __shared__ __align__(16) float sm[SMEM_FLOATS];
    int tid = threadIdx.x;
    int w = tid >> 5, lane = tid & 31;
    uint32_t rank;
    asm("mov.u32 %0, %%cluster_ctarank;" : "=r"(rank));
    int colg = (int)rank * 64;
    int bm0 = ((int)blockIdx.x >> 2) * 4;

    // Wx1 slice -> padded smem [64][68]
    for (int idx = tid; idx < 64 * 64; idx += THREADS) {
        int k = idx >> 6, c = idx & 63;
        sm[OFF_WX1 + k * 68 + c] = Wx1[k * HH + colg + c];
    }
    // zero h1+h2 (contiguous)
    for (int i = tid; i < 4608; i += THREADS) sm[OFF_H1 + i] = 0.f;

    // recurrent weights -> registers: lane owns k in [8*lane, 8*lane+8),
    // warp owns cols colg + [4w, 4w+4)
    float wh1[32], wx2[32], wh2[32];
#pragma unroll
    for (int c = 0; c < 4; c++) {
#pragma unroll
        for (int i = 0; i < 8; i++) {
            int k = 8 * lane + i;
            int col = colg + 4 * w + c;
            wh1[c * 8 + i] = Wh1[k * HH + col];
            wx2[c * 8 + i] = Wx2[k * HH + col];
            wh2[c * 8 + i] = Wh2[k * HH + col];
        }
    }
    int colf = colg + 4 * w + (lane >> 3);      // this lane's finalize column
    float b1c = b1[colf], b2c = b2[colf];
    uint32_t sh16 = 16u * (uint32_t)(colf + (colf >> 3));   // swizzled h slot byte off
    uint32_t su = s2u(sm);
    uint32_t lane144 = 144u * (uint32_t)lane;   // 16 * 9 * lane (h slice base)

    if (tid == 0) {
        mbar_init(su + MBAR1_B, 1);
        mbar_init(su + MBAR2_B, 1);
    }
    // stage x(0) swizzled: slot s_x(k)=k+(k>>1)
    int xk = tid >> 2, xm = tid & 3;
    int sxi = (xk + (xk >> 1)) * 4 + xm;
    const size_t xbase = (size_t)(bm0 + xm) * TT * DD + xk;
    if (tid < 256) sm[OFF_XT + sxi] = x[xbase];
    __syncthreads();
    CLUSTER_SYNC();   // mbarriers + buffers live before any st.async

    // initial L1(0) partials (h1(-1)=0 in parity-1 buffer)
    ull acc[8] = {0, 0, 0, 0, 0, 0, 0, 0};
    accumX(su + OFF_WX1 * 4, w, lane, su + OFF_XT * 4, acc);
    accumR(wh1, su + (OFF_H1 + 1152) * 4 + lane144, acc);

#pragma unroll 1
    for (int t = 0; t < TT; t++) {
        int p = t & 1, pn = p ^ 1;
        if (tid == 0) {
            mbar_expect(su + MBAR1_B, 4096);
            mbar_expect(su + MBAR2_B, 4096);
        }
        // ---- phase A: finish layer 1, broadcast h1(t) ----
        wreduce(acc, lane);
        finalize(acc, lane, b1c, su, (uint32_t)(OFF_H1 + p * 1152) * 4, sh16, MBAR1_B);
        // hidden: Wh2*h2(t-1) + x prefetch
#pragma unroll
        for (int j = 0; j < 8; j++) acc[j] = 0;
        accumR(wh2, su + (OFF_H2 + pn * 1152) * 4 + lane144, acc);
        if (t + 1 < TT && tid < 256)
            sm[OFF_XT + pn * 384 + sxi] = x[xbase + (size_t)(t + 1) * DD];
        mbar_wait(su + MBAR1_B, (uint32_t)p);
        __syncthreads();                         // xT[pn] staging visible

        // ---- phase B: Wx2*h1(t), finish layer 2, broadcast h2(t) ----
        accumR(wx2, su + (OFF_H1 + p * 1152) * 4 + lane144, acc);
        wreduce(acc, lane);
        finalize(acc, lane, b2c, su, (uint32_t)(OFF_H2 + p * 1152) * 4, sh16, MBAR2_B);
        // hidden: L1(t+1) = Wx1*x(t+1) + Wh1*h1(t)
#pragma unroll
        for (int j = 0; j < 8; j++) acc[j] = 0;
        if (t + 1 < TT) {
            accumX(su + OFF_WX1 * 4, w, lane, su + (OFF_XT + pn * 384) * 4, acc);
            accumR(wh1, su + (OFF_H1 + p * 1152) * 4 + lane144, acc);
        }
        mbar_wait(su + MBAR2_B, (uint32_t)p);
    }
    __syncthreads();

    // ---- epilogue: each rank outputs its own batch row (h2 replicated) ----
    {
        const float* h2f = sm + OFF_H2 + 1152;   // parity of t=1023 is 1
        int kq = tid >> 7, o = tid & 127;
        float part = 0.f;
#pragma unroll 8
        for (int i = 0; i < 64; i++) {
            int k = kq * 64 + i;
            part += h2f[(k + (k >> 3)) * 4 + (int)rank] * Wd[k * OO + o];
        }
        sm[OFF_SCR + kq * 128 + o] = part;
        __syncthreads();
        if (tid < 128) {
            float l = bd[tid] + sm[OFF_SCR + tid] + sm[OFF_SCR + 128 + tid]
                    + sm[OFF_SCR + 256 + tid] + sm[OFF_SCR + 384 + tid];
            sm[OFF_SCR + 512 + tid] = l;
        }
        __syncthreads();
        if (tid < 32) {
            const float* L = sm + OFF_SCR + 512;
            float v0 = L[tid], v1 = L[tid + 32], v2 = L[tid + 64], v3 = L[tid + 96];
            float mx = fmaxf(fmaxf(v0, v1), fmaxf(v2, v3));
#pragma unroll
            for (int s = 16; s; s >>= 1) mx = fmaxf(mx, __shfl_xor_sync(0xffffffffu, mx, s));
            float e0 = __expf(v0 - mx), e1 = __expf(v1 - mx);
            float e2 = __expf(v2 - mx), e3 = __expf(v3 - mx);
            float ssum = e0 + e1 + e2 + e3;
#pragma unroll
            for (int s = 16; s; s >>= 1) ssum += __shfl_xor_sync(0xffffffffu, ssum, s);
            float inv = 1.f / ssum;
            float* orow = out + (size_t)(bm0 + (int)rank) * OO;
            orow[tid] = e0 * inv;
            orow[tid + 32] = e1 * inv;
            orow[tid + 64] = e2 * inv;
            orow[tid + 96] = e3 * inv;
        }
    }
    CLUSTER_SYNC();   // keep cluster alive until all in-flight st.async land
}

extern "C" void kernel_launch(void* const* d_in, const int* in_sizes, int n_in,
                              void* d_out, int out_size) {
    rnn_kernel<<<128, THREADS>>>(
        (const float*)d_in[0], (const float*)d_in[1], (const float*)d_in[2],
        (const float*)d_in[3], (const float*)d_in[4], (const float*)d_in[5],
        (const float*)d_in[6], (const float*)d_in[7], (const float*)d_in[8],
        (float*)d_out);
}